// round 8
// baseline (speedup 1.0000x reference)
#include <cuda_runtime.h>

// ---------------------------------------------------------------------------
// Problem constants
// ---------------------------------------------------------------------------
#define BATCH   8
#define CH      64        // C_IN == C_OUT == GROUPS == 64  (depthwise)
#define HH      256
#define WW      256
#define KK      3
#define REP_DIM 512
#define NFEAT   (CH * KK * KK)   // 576
#define ROWS_PER_WARP 4

// Scratch for the per-sample dynamic 3x3 kernels (post leaky-relu).
__device__ float g_kern[BATCH * NFEAT];

// ---------------------------------------------------------------------------
// Stage 1 (v2): one warp per feature f; each warp reads its w_key row ONCE
// and accumulates the dot against all 8 batch representations simultaneously.
// w_key traffic drops 8x vs warp-per-(b,f); rep (16 KB) stays L1-resident.
// ---------------------------------------------------------------------------
__global__ __launch_bounds__(256)
void keygen_kernel(const float* __restrict__ rep,
                   const float* __restrict__ wkey) {
    const int gid  = blockIdx.x * blockDim.x + threadIdx.x;
    const int f    = gid >> 5;          // warp id == feature
    const int lane = gid & 31;
    if (f >= NFEAT) return;

    const float4* w4 = reinterpret_cast<const float4*>(wkey + (size_t)f * REP_DIM);

    float s[BATCH];
    #pragma unroll
    for (int b = 0; b < BATCH; b++) s[b] = 0.0f;

    #pragma unroll
    for (int i = lane; i < REP_DIM / 4; i += 32) {
        const float4 w = w4[i];
        #pragma unroll
        for (int b = 0; b < BATCH; b++) {
            const float4 a = reinterpret_cast<const float4*>(rep + b * REP_DIM)[i];
            s[b] += a.x * w.x + a.y * w.y + a.z * w.z + a.w * w.w;
        }
    }

    #pragma unroll
    for (int b = 0; b < BATCH; b++) {
        #pragma unroll
        for (int o = 16; o > 0; o >>= 1)
            s[b] += __shfl_xor_sync(0xffffffffu, s[b], o);
    }

    if (lane == 0) {
        #pragma unroll
        for (int b = 0; b < BATCH; b++) {
            float v = s[b];
            g_kern[b * NFEAT + f] = (v > 0.0f) ? v : 0.1f * v;
        }
    }
}

// ---------------------------------------------------------------------------
// Row loader: one warp loads a full 256-float row as 2 coalesced float4s per
// lane and resolves ALL horizontal halos (interior + mid-row seam +
// reflection edges) with warp shuffles. Zero scalar LDGs.
//
// r[0..5]  = [left halo, v0.x, v0.y, v0.z, v0.w, right halo]  (w 0..127)
// r[6..11] = [left halo, v1.x, v1.y, v1.z, v1.w, right halo]  (w 128..255)
// ---------------------------------------------------------------------------
__device__ __forceinline__ void load_row(const float* __restrict__ row,
                                         int lane, float* r) {
    const unsigned FULL = 0xffffffffu;
    float4 v0 = *reinterpret_cast<const float4*>(row + lane * 4);
    float4 v1 = *reinterpret_cast<const float4*>(row + 128 + lane * 4);

    float up0  = __shfl_up_sync  (FULL, v0.w, 1);   // elem 4j-1   (j>0)
    float dn0  = __shfl_down_sync(FULL, v0.x, 1);   // elem 4j+4   (j<31)
    float b10  = __shfl_sync     (FULL, v1.x, 0);   // elem 128    (seam)
    float up1  = __shfl_up_sync  (FULL, v1.w, 1);   // elem 127+4j (j>0)
    float b031 = __shfl_sync     (FULL, v0.w, 31);  // elem 127    (seam)
    float dn1  = __shfl_down_sync(FULL, v1.x, 1);   // elem 132+4j (j<31)

    // Reflection pad: w=-1 -> w=1 (lane0 own v0.y); w=256 -> w=254 (lane31 own v1.z)
    r[0]  = (lane == 0)  ? v0.y : up0;
    r[1]  = v0.x; r[2] = v0.y; r[3] = v0.z; r[4] = v0.w;
    r[5]  = (lane == 31) ? b10  : dn0;
    r[6]  = (lane == 0)  ? b031 : up1;
    r[7]  = v1.x; r[8] = v1.y; r[9] = v1.z; r[10] = v1.w;
    r[11] = (lane == 31) ? v1.z : dn1;
}

// ---------------------------------------------------------------------------
// Stage 2: per-sample depthwise 3x3 conv with reflection padding (pad=1).
// grid: (HH/(8*ROWS_PER_WARP), CH, BATCH), block: (32, 8).
// One warp computes 4 consecutive output rows with a rolling 3-row register
// buffer (6 row loads per 4 output rows).
//
// PDL: launched with programmatic stream serialization. The priming image
// loads are issued BEFORE cudaGridDependencySynchronize(), overlapping the
// keygen kernel; the dynamic taps (keygen's output) are read only after it.
// ---------------------------------------------------------------------------
__global__ __launch_bounds__(256)
void dwconv_kernel(const float* __restrict__ x, float* __restrict__ out) {
    const int lane = threadIdx.x;                                  // 0..31
    const int h0   = (blockIdx.x * 8 + threadIdx.y) * ROWS_PER_WARP;
    const int c    = blockIdx.y;
    const int b    = blockIdx.z;

    const float* img = x + ((size_t)(b * CH + c)) * HH * WW;
    float* dst_base  = out + ((size_t)(b * CH + c)) * HH * WW;

    // Rolling 3-row register buffer. Prime rows h0-1 (reflected) and h0 —
    // these loads do NOT depend on keygen, issue them before the PDL sync.
    float R[3][12];
    {
        const int hm = (h0 == 0) ? 1 : h0 - 1;   // reflect top edge
        load_row(img + (size_t)hm * WW, lane, R[0]);
        load_row(img + (size_t)h0 * WW, lane, R[1]);
    }

    // Wait for keygen grid completion (memory visible), then read taps.
    cudaGridDependencySynchronize();

    const float* kp = &g_kern[(b * CH + c) * (KK * KK)];
    const float k00 = __ldg(kp + 0), k01 = __ldg(kp + 1), k02 = __ldg(kp + 2);
    const float k10 = __ldg(kp + 3), k11 = __ldg(kp + 4), k12 = __ldg(kp + 5);
    const float k20 = __ldg(kp + 6), k21 = __ldg(kp + 7), k22 = __ldg(kp + 8);

    #pragma unroll
    for (int i = 0; i < ROWS_PER_WARP; i++) {
        const int h  = h0 + i;
        const int hn = (h == HH - 1) ? HH - 2 : h + 1;  // reflect bottom edge
        load_row(img + (size_t)hn * WW, lane, R[(i + 2) % 3]);

        const float* rA = R[i % 3];        // row h-1
        const float* rB = R[(i + 1) % 3];  // row h
        const float* rC = R[(i + 2) % 3];  // row h+1

        float4 oA, oB;
        float* a  = &oA.x;
        float* bb = &oB.x;
        #pragma unroll
        for (int j = 0; j < 4; j++) {
            a[j]  = k00 * rA[j]     + k01 * rA[j + 1] + k02 * rA[j + 2]
                  + k10 * rB[j]     + k11 * rB[j + 1] + k12 * rB[j + 2]
                  + k20 * rC[j]     + k21 * rC[j + 1] + k22 * rC[j + 2];
            bb[j] = k00 * rA[j + 6] + k01 * rA[j + 7] + k02 * rA[j + 8]
                  + k10 * rB[j + 6] + k11 * rB[j + 7] + k12 * rB[j + 8]
                  + k20 * rC[j + 6] + k21 * rC[j + 7] + k22 * rC[j + 8];
        }

        float* dst = dst_base + (size_t)h * WW;
        __stcs(reinterpret_cast<float4*>(dst + lane * 4), oA);
        __stcs(reinterpret_cast<float4*>(dst + 128 + lane * 4), oB);
    }
}

// ---------------------------------------------------------------------------
// Launch
// Inputs (metadata order): d_in[0]=x [8,64,256,256] f32,
//                          d_in[1]=representation [8,512] f32,
//                          d_in[2]=w_key [576,512] f32
// Output: f32 [8,64,256,256]
// ---------------------------------------------------------------------------
extern "C" void kernel_launch(void* const* d_in, const int* in_sizes, int n_in,
                              void* d_out, int out_size) {
    const float* x    = (const float*)d_in[0];
    const float* rep  = (const float*)d_in[1];
    const float* wkey = (const float*)d_in[2];
    float* out        = (float*)d_out;

    // Stage 1: 576 warps (one per feature) -> 72 blocks of 256 threads
    keygen_kernel<<<(NFEAT * 32 + 255) / 256, 256>>>(rep, wkey);

    // Stage 2: depthwise conv, PDL-overlapped with stage 1.
    {
        cudaLaunchConfig_t cfg = {};
        cfg.gridDim  = dim3(HH / (8 * ROWS_PER_WARP), CH, BATCH);  // (8,64,8)
        cfg.blockDim = dim3(32, 8);
        cfg.stream   = 0;

        cudaLaunchAttribute attr[1];
        attr[0].id = cudaLaunchAttributeProgrammaticStreamSerialization;
        attr[0].val.programmaticStreamSerializationAllowed = 1;
        cfg.attrs    = attr;
        cfg.numAttrs = 1;

        cudaLaunchKernelEx(&cfg, dwconv_kernel, x, out);
    }
}